// round 10
// baseline (speedup 1.0000x reference)
#include <cuda_runtime.h>
#include <cuda_fp16.h>
#include <cstdint>

// ---------------------------------------------------------------------------
// LightGCN on B200 (sm_100a) — CSR-gather, fp16 folded-weight states,
// 8-lane/row uint4 gathers.
//   Trick: store x'[c] = dis[c]*x[c] (fp16). Gather = pure sum S = sum x'[col].
//   y'_{l+1}[r] = dis[r]^2 * S. Epilogue: x_l[r] = idis[r]*y'_l[r].
//   CSR holds only col (4 B/edge). Math fp32; storage fp16.
// ---------------------------------------------------------------------------

#define NUM_USERS   100000
#define NUM_ST      150000
#define NUM_INTENTS 6000
#define N_NODES     (NUM_USERS + NUM_ST + NUM_INTENTS)   // 256000
#define EMBED_DIM   64
#define N_EDGES     4000000

#define NFLOATS     (N_NODES * EMBED_DIM)        // 16,384,000
#define NF8         (NFLOATS / 8)                // 2,048,000
#define DETECT_N    4096

#define SCAN_BLOCK  1024
#define NBLK        (N_NODES / SCAN_BLOCK)       // 250 (exact)

// half2 <-> u32 reinterpret helpers
__device__ __forceinline__ unsigned h2u(__half2 h) {
    return *reinterpret_cast<unsigned*>(&h);
}
__device__ __forceinline__ __half2 u2h(unsigned u) {
    return *reinterpret_cast<__half2*>(&u);
}

// Scratch (device globals: allocation-guard safe)
__device__ __align__(16) __half g_e [NFLOATS];   // emb' = dis*emb   (fp16)
__device__ __align__(16) __half g_h1[NFLOATS];   // y1' = dis*x1     (fp16)
__device__ __align__(16) __half g_h2[NFLOATS];   // y2' = dis*x2     (fp16)
__device__ float g_dis [N_NODES];    // deg^-1/2 (0 if deg==0)
__device__ float g_idis[N_NODES];    // deg^+1/2 (0 if deg==0)
__device__ int   g_deg[N_NODES];
__device__ int   g_start[N_NODES];     // CSR row start (exclusive scan)
__device__ int   g_cursor[N_NODES];    // fill cursor; after fill = row end
__device__ int   g_bsum[NBLK];
__device__ int   g_bsumx[NBLK];
__device__ int   g_csr_col[N_EDGES];   // col only (4 B/edge)
__device__ int   g_not64;   // 1 => edge data is int32

// ---------------------------------------------------------------------------

// Zero degrees + dtype detection in one launch.
__global__ void k_zero_detect(const long long* __restrict__ ei) {
    int i = blockIdx.x * blockDim.x + threadIdx.x;
    if (i < N_NODES) g_deg[i] = 0;
    if (i == 0) g_not64 = 0;
    __threadfence();
    if (i < DETECT_N) {
        long long v = ei[i];
        if (v < 0 || v >= N_NODES) atomicOr(&g_not64, 1);
    }
}

// Degree histogram straight from edge_index (row half only).
__global__ void k_deg(const void* __restrict__ eiv) {
    int e = blockIdx.x * blockDim.x + threadIdx.x;
    if (e >= N_EDGES) return;
    long long r64;
    if (g_not64) r64 = ((const int*)eiv)[e];
    else         r64 = ((const long long*)eiv)[e];
    if (r64 >= 0 && r64 < N_NODES) atomicAdd(&g_deg[(int)r64], 1);
}

// ---- exclusive prefix sum over g_deg (3 kernels) ----

__global__ void k_scan1() {
    __shared__ int sh[SCAN_BLOCK];
    int i = blockIdx.x * SCAN_BLOCK + threadIdx.x;
    int v = g_deg[i];
    sh[threadIdx.x] = v;
    __syncthreads();
    for (int off = 1; off < SCAN_BLOCK; off <<= 1) {
        int t = (threadIdx.x >= off) ? sh[threadIdx.x - off] : 0;
        __syncthreads();
        sh[threadIdx.x] += t;
        __syncthreads();
    }
    g_start[i] = sh[threadIdx.x];   // inclusive-within-block (temp)
    if (threadIdx.x == SCAN_BLOCK - 1) g_bsum[blockIdx.x] = sh[threadIdx.x];
}

__global__ void k_scan2() {   // single block of 256 threads, NBLK=250
    __shared__ int sh[256];
    int v = (threadIdx.x < NBLK) ? g_bsum[threadIdx.x] : 0;
    sh[threadIdx.x] = v;
    __syncthreads();
    for (int off = 1; off < 256; off <<= 1) {
        int t = (threadIdx.x >= off) ? sh[threadIdx.x - off] : 0;
        __syncthreads();
        sh[threadIdx.x] += t;
        __syncthreads();
    }
    if (threadIdx.x < NBLK) g_bsumx[threadIdx.x] = sh[threadIdx.x] - v; // exclusive
}

// scan fixup + dis/idis (merged; deg already at hand)
__global__ void k_scan3() {
    int i = blockIdx.x * blockDim.x + threadIdx.x;
    if (i >= N_NODES) return;
    int d = g_deg[i];
    int excl = g_start[i] - d + g_bsumx[i / SCAN_BLOCK];
    g_start[i]  = excl;
    g_cursor[i] = excl;
    float df = (float)d;
    g_dis[i]  = (d > 0) ? rsqrtf(df) : 0.0f;
    g_idis[i] = (d > 0) ? sqrtf(df)  : 0.0f;
}

// Fill CSR: col only (weights folded into states).
__global__ void k_fill(const void* __restrict__ eiv) {
    int e = blockIdx.x * blockDim.x + threadIdx.x;
    if (e >= N_EDGES) return;
    long long r64, c64;
    if (g_not64) {
        const int* ei32 = (const int*)eiv;
        r64 = ei32[e];
        c64 = ei32[N_EDGES + e];
    } else {
        const long long* ei64 = (const long long*)eiv;
        r64 = ei64[e];
        c64 = ei64[(long long)N_EDGES + e];
    }
    if (r64 < 0 || r64 >= N_NODES || c64 < 0 || c64 >= N_NODES) return;
    int r = (int)r64, c = (int)c64;
    int p = atomicAdd(&g_cursor[r], 1);
    g_csr_col[p] = c;
}

// emb' = fp16(dis[n] * emb[n]) — one uint4 (8 halves) per thread
__global__ void k_prescale(const float4* __restrict__ emb,
                           uint4* __restrict__ ep) {
    int i = blockIdx.x * blockDim.x + threadIdx.x;   // NF8 threads
    if (i >= NF8) return;
    int n = i >> 3;                 // 8 uint4 per node row
    float dr = g_dis[n];
    float4 v0 = __ldcs(&emb[i * 2]);
    float4 v1 = __ldcs(&emb[i * 2 + 1]);
    uint4 pk;
    pk.x = h2u(__float22half2_rn(make_float2(dr * v0.x, dr * v0.y)));
    pk.y = h2u(__float22half2_rn(make_float2(dr * v0.z, dr * v0.w)));
    pk.z = h2u(__float22half2_rn(make_float2(dr * v1.x, dr * v1.y)));
    pk.w = h2u(__float22half2_rn(make_float2(dr * v1.z, dr * v1.w)));
    __stcs(&ep[i], pk);
}

// ---------------------------------------------------------------------------
// Gathers: 8 threads per row, one uint4 (8 halves = 8 dims) lane each.
//   S[r] = sum_{e in row} x'[col]   (pure sum, weights pre-folded)
// ---------------------------------------------------------------------------

struct F8 { float v[8]; };

__device__ __forceinline__ void row_gather_sum8(const uint4* __restrict__ x,
                                                int r, int c, unsigned gmask,
                                                F8& acc) {
    int start = g_start[r];
    int end   = g_cursor[r];
    #pragma unroll
    for (int k = 0; k < 8; ++k) acc.v[k] = 0.f;
    for (int base = start; base < end; base += 8) {
        int n = min(8, end - base);
        int cl = 0;
        if (c < n) cl = __ldcs(&g_csr_col[base + c]);
        #pragma unroll 8
        for (int j = 0; j < n; ++j) {
            int col  = __shfl_sync(gmask, cl, j, 8);
            uint4 hv = __ldg(&x[col * 8 + c]);
            float2 f0 = __half22float2(u2h(hv.x));
            float2 f1 = __half22float2(u2h(hv.y));
            float2 f2 = __half22float2(u2h(hv.z));
            float2 f3 = __half22float2(u2h(hv.w));
            acc.v[0] += f0.x; acc.v[1] += f0.y;
            acc.v[2] += f1.x; acc.v[3] += f1.y;
            acc.v[4] += f2.x; acc.v[5] += f2.y;
            acc.v[6] += f3.x; acc.v[7] += f3.y;
        }
    }
}

// Layers 1..2: y'[r] = fp16(dis[r]^2 * S)
__global__ void k_gather(const uint4* __restrict__ x,
                         uint4* __restrict__ y) {
    int t = blockIdx.x * blockDim.x + threadIdx.x;   // N_NODES*8 = 2,048,000
    int r = t >> 3;
    int c = t & 7;
    if (r >= N_NODES) return;
    unsigned gmask = 0xFFu << (threadIdx.x & 24);
    F8 acc;
    row_gather_sum8(x, r, c, gmask, acc);
    float dr = g_dis[r];
    float s = dr * dr;
    uint4 pk;
    pk.x = h2u(__float22half2_rn(make_float2(s * acc.v[0], s * acc.v[1])));
    pk.y = h2u(__float22half2_rn(make_float2(s * acc.v[2], s * acc.v[3])));
    pk.z = h2u(__float22half2_rn(make_float2(s * acc.v[4], s * acc.v[5])));
    pk.w = h2u(__float22half2_rn(make_float2(s * acc.v[6], s * acc.v[7])));
    __stcs(&y[r * 8 + c], pk);
}

// Layer 3 + fused epilogue: out = 0.25*(emb + idis[r]*(y1'+y2') + dis[r]*S3)
__global__ void k_gather_final(const uint4* __restrict__ y2,
                               const float4* __restrict__ emb,
                               const uint4* __restrict__ y1,
                               float4* __restrict__ out) {
    int t = blockIdx.x * blockDim.x + threadIdx.x;
    int r = t >> 3;
    int c = t & 7;
    if (r >= N_NODES) return;
    unsigned gmask = 0xFFu << (threadIdx.x & 24);
    F8 acc;
    row_gather_sum8(y2, r, c, gmask, acc);
    float dr = g_dis[r];
    float ir = g_idis[r];
    int idx8 = r * 8 + c;            // uint4 index
    int idx4 = idx8 * 2;             // float4 index
    uint4 h1 = __ldcs(&y1[idx8]);
    uint4 h2 = __ldcs(&y2[idx8]);
    float4 e0 = __ldcs(&emb[idx4]);
    float4 e1 = __ldcs(&emb[idx4 + 1]);

    float2 a1[4] = { __half22float2(u2h(h1.x)), __half22float2(u2h(h1.y)),
                     __half22float2(u2h(h1.z)), __half22float2(u2h(h1.w)) };
    float2 a2[4] = { __half22float2(u2h(h2.x)), __half22float2(u2h(h2.y)),
                     __half22float2(u2h(h2.z)), __half22float2(u2h(h2.w)) };

    float4 o0, o1;
    o0.x = 0.25f * (e0.x + ir * (a1[0].x + a2[0].x) + dr * acc.v[0]);
    o0.y = 0.25f * (e0.y + ir * (a1[0].y + a2[0].y) + dr * acc.v[1]);
    o0.z = 0.25f * (e0.z + ir * (a1[1].x + a2[1].x) + dr * acc.v[2]);
    o0.w = 0.25f * (e0.w + ir * (a1[1].y + a2[1].y) + dr * acc.v[3]);
    o1.x = 0.25f * (e1.x + ir * (a1[2].x + a2[2].x) + dr * acc.v[4]);
    o1.y = 0.25f * (e1.y + ir * (a1[2].y + a2[2].y) + dr * acc.v[5]);
    o1.z = 0.25f * (e1.z + ir * (a1[3].x + a2[3].x) + dr * acc.v[6]);
    o1.w = 0.25f * (e1.w + ir * (a1[3].y + a2[3].y) + dr * acc.v[7]);
    __stcs(&out[idx4], o0);
    __stcs(&out[idx4 + 1], o1);
}

// ---------------------------------------------------------------------------

extern "C" void kernel_launch(void* const* d_in, const int* in_sizes, int n_in,
                              void* d_out, int out_size) {
    // Input-order detection by element count (dtype-independent).
    int ei_idx = 1, emb_idx = 0;
    if (n_in >= 2 && in_sizes[0] == 2 * N_EDGES) { ei_idx = 0; emb_idx = 1; }

    const float* emb = (const float*)d_in[emb_idx];
    const void*  ei  = d_in[ei_idx];
    float*       out = (float*)d_out;

    const int TB = 256;
    const int node_blocks = (N_NODES + TB - 1) / TB;
    const int edge_blocks = (N_EDGES + TB - 1) / TB;
    const int f8_blocks   = (NF8 + TB - 1) / TB;
    const int gat_blocks  = (N_NODES * 8 + TB - 1) / TB;   // 2M threads

    __half* e;   cudaGetSymbolAddress((void**)&e,  g_e);
    __half* h1;  cudaGetSymbolAddress((void**)&h1, g_h1);
    __half* h2;  cudaGetSymbolAddress((void**)&h2, g_h2);

    // ---- preprocess: degrees, scan(+dis), CSR, fp16 prescaled emb ----
    k_zero_detect<<<node_blocks, TB>>>((const long long*)ei);
    k_deg<<<edge_blocks, TB>>>(ei);
    k_scan1<<<NBLK, SCAN_BLOCK>>>();
    k_scan2<<<1, 256>>>();
    k_scan3<<<node_blocks, TB>>>();
    k_fill<<<edge_blocks, TB>>>(ei);
    k_prescale<<<f8_blocks, TB>>>((const float4*)emb, (uint4*)e);

    // ---- 3 gather layers; epilogue fused into the last ----
    k_gather<<<gat_blocks, TB>>>((const uint4*)e,  (uint4*)h1);   // y1'
    k_gather<<<gat_blocks, TB>>>((const uint4*)h1, (uint4*)h2);   // y2'
    k_gather_final<<<gat_blocks, TB>>>((const uint4*)h2,
                                       (const float4*)emb,
                                       (const uint4*)h1,
                                       (float4*)out);
}